// round 7
// baseline (speedup 1.0000x reference)
#include <cuda_runtime.h>
#include <cuda_bf16.h>
#include <cstdint>

#define BATCH 512
#define SEQ 256
#define EMBED 384
#define HD 64
#define M_TOTAL (BATCH*SEQ)
#define NTOT 192          // Q|K|V output columns
#define PA 56             // proj smem pitch (bf16): 112B rows, conflict-free ldsm
#define KP 72             // attn smem pitch (bf16): 144B rows, conflict-free ldsm
#define KPW 36            // attn pitch in u32

// bf16 hi/lo scratch for projected Q (pre-scaled), K, V.
__device__ __nv_bfloat16 g_Qh[(size_t)M_TOTAL*HD];
__device__ __nv_bfloat16 g_Ql[(size_t)M_TOTAL*HD];
__device__ __nv_bfloat16 g_Kh[(size_t)M_TOTAL*HD];
__device__ __nv_bfloat16 g_Kl[(size_t)M_TOTAL*HD];
__device__ __nv_bfloat16 g_Vh[(size_t)M_TOTAL*HD];
__device__ __nv_bfloat16 g_Vl[(size_t)M_TOTAL*HD];
// W pre-transposed to [n=192][k=384], split into bf16 hi/lo. Q-scale folded in.
__device__ __nv_bfloat16 g_Wh[NTOT*EMBED];
__device__ __nv_bfloat16 g_Wl[NTOT*EMBED];

__global__ void prep_kernel(const float* __restrict__ Wq,
                            const float* __restrict__ Wk,
                            const float* __restrict__ Wv)
{
    int idx = blockIdx.x * 256 + threadIdx.x;
    int n = idx / EMBED;
    int k = idx - n * EMBED;
    const float* W = (n < 64) ? Wq : (n < 128) ? Wk : Wv;
    float v = W[(size_t)k * HD + (n & 63)];
    if (n < 64) v *= 0.125f;
    __nv_bfloat16 h = __float2bfloat16(v);
    g_Wh[idx] = h;
    g_Wl[idx] = __float2bfloat16(v - __bfloat162float(h));
}

__device__ __forceinline__ void mma_bf16(float* d, const uint32_t* a, const uint32_t* b) {
    asm volatile(
        "mma.sync.aligned.m16n8k16.row.col.f32.bf16.bf16.f32 "
        "{%0,%1,%2,%3}, {%4,%5,%6,%7}, {%8,%9}, {%0,%1,%2,%3};\n"
        : "+f"(d[0]), "+f"(d[1]), "+f"(d[2]), "+f"(d[3])
        : "r"(a[0]), "r"(a[1]), "r"(a[2]), "r"(a[3]), "r"(b[0]), "r"(b[1]));
}
__device__ __forceinline__ void ldsm4(uint32_t r[4], uint32_t a) {
    asm volatile("ldmatrix.sync.aligned.m8n8.x4.shared.b16 {%0,%1,%2,%3}, [%4];\n"
        : "=r"(r[0]), "=r"(r[1]), "=r"(r[2]), "=r"(r[3]) : "r"(a));
}
__device__ __forceinline__ void ldsm4t(uint32_t r[4], uint32_t a) {
    asm volatile("ldmatrix.sync.aligned.m8n8.x4.trans.shared.b16 {%0,%1,%2,%3}, [%4];\n"
        : "=r"(r[0]), "=r"(r[1]), "=r"(r[2]), "=r"(r[3]) : "r"(a));
}
__device__ __forceinline__ uint32_t sptr(const void* p) {
    return (uint32_t)__cvta_generic_to_shared(p);
}
__device__ __forceinline__ void pack2(float x, float y, uint32_t& h, uint32_t& l) {
    __nv_bfloat162 hh = __floats2bfloat162_rn(x, y);
    __nv_bfloat162 ll = __floats2bfloat162_rn(x - __low2float(hh), y - __high2float(hh));
    h = *reinterpret_cast<uint32_t*>(&hh);
    l = *reinterpret_cast<uint32_t*>(&ll);
}

// ---------------------------------------------------------------------------
// Projection: C[131072,192] = X x W on tensor cores, bf16 2-term split.
// Block 128x192xk32, 8 warps of 64x48. Fragments via ldmatrix. bf16 hi/lo out.
// ---------------------------------------------------------------------------
__global__ __launch_bounds__(256, 1) void proj_kernel(const float* __restrict__ X)
{
    extern __shared__ char smem_raw[];
    __nv_bfloat16* Ah = (__nv_bfloat16*)smem_raw;           // [128][PA]
    __nv_bfloat16* Al = Ah + 128 * PA;
    __nv_bfloat16* Bh = Al + 128 * PA;                      // [192][PA]
    __nv_bfloat16* Bl = Bh + NTOT * PA;

    const int tid   = threadIdx.x;
    const int lane  = tid & 31;
    const int warp  = tid >> 5;
    const int g     = lane >> 2;
    const int t     = lane & 3;
    const int warpM = warp & 1;
    const int warpN = warp >> 1;
    const int row0  = blockIdx.x * 128;

    // ldmatrix per-lane byte offsets
    const int arow = (lane & 15) * (PA * 2) + (lane >> 4) * 16;                       // A m16k16
    const int brow = (((lane >> 4) << 3) + (lane & 7)) * (PA * 2) + ((lane >> 3) & 1) * 16; // B n16k16
    const uint32_t sAh = sptr(Ah), sAl = sptr(Al), sBh = sptr(Bh), sBl = sptr(Bl);

    float acc[4][6][4];
    #pragma unroll
    for (int mt = 0; mt < 4; mt++)
        #pragma unroll
        for (int nt = 0; nt < 6; nt++)
            #pragma unroll
            for (int c = 0; c < 4; c++) acc[mt][nt][c] = 0.f;

    float4 xr[4];
    int4 wr[6];
    #pragma unroll
    for (int p = 0; p < 4; p++) {
        int idx = tid + p * 256;
        int r = idx >> 3, kq = (idx & 7) * 4;
        xr[p] = *(const float4*)(X + (size_t)(row0 + r) * EMBED + kq);
    }
    #pragma unroll
    for (int p = 0; p < 3; p++) {
        int idx = tid + p * 256;
        int n = idx >> 2, q4 = idx & 3;
        wr[p]     = *(const int4*)(g_Wh + (size_t)n * EMBED + q4 * 8);
        wr[p + 3] = *(const int4*)(g_Wl + (size_t)n * EMBED + q4 * 8);
    }

    for (int ch = 0; ch < 12; ch++) {
        #pragma unroll
        for (int p = 0; p < 4; p++) {
            int idx = tid + p * 256;
            int r = idx >> 3, kq = (idx & 7) * 4;
            float4 v = xr[p];
            __nv_bfloat162 h01 = __floats2bfloat162_rn(v.x, v.y);
            __nv_bfloat162 h23 = __floats2bfloat162_rn(v.z, v.w);
            __nv_bfloat162 l01 = __floats2bfloat162_rn(v.x - __low2float(h01),
                                                       v.y - __high2float(h01));
            __nv_bfloat162 l23 = __floats2bfloat162_rn(v.z - __low2float(h23),
                                                       v.w - __high2float(h23));
            *(__nv_bfloat162*)(Ah + r * PA + kq)     = h01;
            *(__nv_bfloat162*)(Ah + r * PA + kq + 2) = h23;
            *(__nv_bfloat162*)(Al + r * PA + kq)     = l01;
            *(__nv_bfloat162*)(Al + r * PA + kq + 2) = l23;
        }
        #pragma unroll
        for (int p = 0; p < 3; p++) {
            int idx = tid + p * 256;
            int n = idx >> 2, q4 = idx & 3;
            *(int4*)(Bh + n * PA + q4 * 8) = wr[p];
            *(int4*)(Bl + n * PA + q4 * 8) = wr[p + 3];
        }
        __syncthreads();

        if (ch < 11) {
            int k0n = (ch + 1) * 32;
            #pragma unroll
            for (int p = 0; p < 4; p++) {
                int idx = tid + p * 256;
                int r = idx >> 3, kq = (idx & 7) * 4;
                xr[p] = *(const float4*)(X + (size_t)(row0 + r) * EMBED + k0n + kq);
            }
            #pragma unroll
            for (int p = 0; p < 3; p++) {
                int idx = tid + p * 256;
                int n = idx >> 2, q4 = idx & 3;
                wr[p]     = *(const int4*)(g_Wh + (size_t)n * EMBED + k0n + q4 * 8);
                wr[p + 3] = *(const int4*)(g_Wl + (size_t)n * EMBED + k0n + q4 * 8);
            }
        }

        #pragma unroll
        for (int kk = 0; kk < 2; kk++) {
            const int kb = kk * 32;   // 16 k-elems = 32 bytes
            uint32_t ah[4][4], al[4][4], bh[6][2], bl[6][2];
            #pragma unroll
            for (int mt = 0; mt < 4; mt++) {
                int rb = (warpM * 64 + mt * 16) * (PA * 2);
                ldsm4(ah[mt], sAh + rb + arow + kb);
                ldsm4(al[mt], sAl + rb + arow + kb);
            }
            #pragma unroll
            for (int np = 0; np < 3; np++) {
                int nb = (warpN * 48 + np * 16) * (PA * 2);
                uint32_t tmp[4];
                ldsm4(tmp, sBh + nb + brow + kb);
                bh[2*np][0] = tmp[0]; bh[2*np][1] = tmp[1];
                bh[2*np+1][0] = tmp[2]; bh[2*np+1][1] = tmp[3];
                ldsm4(tmp, sBl + nb + brow + kb);
                bl[2*np][0] = tmp[0]; bl[2*np][1] = tmp[1];
                bl[2*np+1][0] = tmp[2]; bl[2*np+1][1] = tmp[3];
            }
            #pragma unroll
            for (int mt = 0; mt < 4; mt++)
                #pragma unroll
                for (int nt = 0; nt < 6; nt++) {
                    mma_bf16(acc[mt][nt], ah[mt], bh[nt]);
                    mma_bf16(acc[mt][nt], al[mt], bh[nt]);
                    mma_bf16(acc[mt][nt], ah[mt], bl[nt]);
                }
        }
        __syncthreads();
    }

    // Epilogue: split to bf16 hi/lo and scatter to Q/K/V.
    #pragma unroll
    for (int mt = 0; mt < 4; mt++) {
        int ra = row0 + warpM * 64 + mt * 16 + g;
        #pragma unroll
        for (int nt = 0; nt < 6; nt++) {
            int col = warpN * 48 + nt * 8 + 2 * t;
            int mat = col >> 6, cc = col & 63;
            __nv_bfloat16* dh = (mat == 0) ? g_Qh : (mat == 1) ? g_Kh : g_Vh;
            __nv_bfloat16* dl = (mat == 0) ? g_Ql : (mat == 1) ? g_Kl : g_Vl;
            float x0 = acc[mt][nt][0], x1 = acc[mt][nt][1];
            __nv_bfloat162 h  = __floats2bfloat162_rn(x0, x1);
            __nv_bfloat162 lo = __floats2bfloat162_rn(x0 - __low2float(h),
                                                      x1 - __high2float(h));
            *(__nv_bfloat162*)(dh + (size_t)ra * HD + cc) = h;
            *(__nv_bfloat162*)(dl + (size_t)ra * HD + cc) = lo;
            x0 = acc[mt][nt][2]; x1 = acc[mt][nt][3];
            h  = __floats2bfloat162_rn(x0, x1);
            lo = __floats2bfloat162_rn(x0 - __low2float(h), x1 - __high2float(h));
            *(__nv_bfloat162*)(dh + (size_t)(ra + 8) * HD + cc) = h;
            *(__nv_bfloat162*)(dl + (size_t)(ra + 8) * HD + cc) = lo;
        }
    }
}

// ---------------------------------------------------------------------------
// Attention on tensor cores. One CTA per batch, 16 warps, one 16-query strip
// per warp (m = w<8 ? w : 23-w -> each SMSP totals 30 chunk-strips).
// Q/K/V (hi/lo) all staged in smem; all fragments are transient ldmatrix
// loads, keeping regs ~100 at 512 threads. No max-tracking (scores bounded).
// ---------------------------------------------------------------------------
__global__ __launch_bounds__(512, 1) void attn_kernel(float* __restrict__ out)
{
    extern __shared__ char smem_raw[];
    __nv_bfloat16* sQh = (__nv_bfloat16*)smem_raw;   // [256][KP]
    __nv_bfloat16* sQl = sQh + SEQ * KP;
    __nv_bfloat16* sKh = sQl + SEQ * KP;
    __nv_bfloat16* sKl = sKh + SEQ * KP;
    __nv_bfloat16* sVh = sKl + SEQ * KP;
    __nv_bfloat16* sVl = sVh + SEQ * KP;

    const int b = blockIdx.x, tid = threadIdx.x;
    const size_t base = (size_t)b * SEQ * HD;

    // Stage all six arrays into padded smem.
    {
        const int4* srcs[6] = {
            (const int4*)(g_Qh + base), (const int4*)(g_Ql + base),
            (const int4*)(g_Kh + base), (const int4*)(g_Kl + base),
            (const int4*)(g_Vh + base), (const int4*)(g_Vl + base)};
        uint32_t* dsts[6] = {(uint32_t*)sQh, (uint32_t*)sQl, (uint32_t*)sKh,
                             (uint32_t*)sKl, (uint32_t*)sVh, (uint32_t*)sVl};
        #pragma unroll
        for (int a = 0; a < 6; a++)
            #pragma unroll
            for (int i = 0; i < 4; i++) {
                int idx = tid + i * 512;
                int row = idx >> 3, c4 = idx & 7;
                *(int4*)(dsts[a] + row * KPW + c4 * 4) = srcs[a][idx];
            }
    }
    __syncthreads();

    const int w = tid >> 5, lane = tid & 31, g = lane >> 2, t = lane & 3;
    const int m = (w < 8) ? w : 23 - w;
    const int q0 = m * 16;

    // ldmatrix per-lane byte offsets
    const int arow = (lane & 15) * (KP * 2) + (lane >> 4) * 16;
    const int brow = (((lane >> 4) << 3) + (lane & 7)) * (KP * 2) + ((lane >> 3) & 1) * 16;
    const int vrow = ((((lane >> 3) & 1) << 3) + (lane & 7)) * (KP * 2) + (lane >> 4) * 16;
    const uint32_t qh_b = sptr(sQh) + q0 * (KP * 2) + arow;
    const uint32_t ql_b = sptr(sQl) + q0 * (KP * 2) + arow;
    const uint32_t kh_b = sptr(sKh) + brow, kl_b = sptr(sKl) + brow;
    const uint32_t vh_b = sptr(sVh) + vrow, vl_b = sptr(sVl) + vrow;

    float O[8][4];
    #pragma unroll
    for (int dt = 0; dt < 8; dt++)
        #pragma unroll
        for (int c = 0; c < 4; c++) O[dt][c] = 0.f;
    float lsum0 = 0.f, lsum1 = 0.f;

    for (int c = 0; c <= m; c++) {
        const int j0b = c * 16 * (KP * 2);

        float S[4][4];
        #pragma unroll
        for (int a = 0; a < 4; a++)
            #pragma unroll
            for (int i = 0; i < 4; i++) S[a][i] = 0.f;

        #pragma unroll
        for (int kk = 0; kk < 4; kk++) {
            uint32_t qh4[4], ql4[4], kh4[4], kl4[4];
            ldsm4(qh4, qh_b + kk * 32);
            ldsm4(ql4, ql_b + kk * 32);
            ldsm4(kh4, kh_b + j0b + kk * 32);
            ldsm4(kl4, kl_b + j0b + kk * 32);
            uint32_t b0h[2] = {kh4[0], kh4[1]}, b1h[2] = {kh4[2], kh4[3]};
            uint32_t b0l[2] = {kl4[0], kl4[1]}, b1l[2] = {kl4[2], kl4[3]};
            int p = kk & 1;
            mma_bf16(S[p],     qh4, b0h);
            mma_bf16(S[2 + p], qh4, b1h);
            mma_bf16(S[p],     ql4, b0h);
            mma_bf16(S[2 + p], ql4, b1h);
            mma_bf16(S[p],     qh4, b0l);
            mma_bf16(S[2 + p], qh4, b1l);
        }

        float p0[4], p1[4];
        #pragma unroll
        for (int i = 0; i < 4; i++) {
            p0[i] = __expf(S[0][i] + S[1][i]);   // cols 2t, 2t+1
            p1[i] = __expf(S[2][i] + S[3][i]);   // cols 2t+8, 2t+9
        }
        if (c == m) {  // diagonal chunk: zero where j > q
            if (2 * t     > g)     p0[0] = 0.f;
            if (2 * t + 1 > g)     p0[1] = 0.f;
            if (2 * t + 8 > g)     p1[0] = 0.f;
            if (2 * t + 9 > g)     p1[1] = 0.f;
            if (2 * t + 8 > g + 8) p1[2] = 0.f;
            if (2 * t + 9 > g + 8) p1[3] = 0.f;
        }
        lsum0 += p0[0] + p0[1] + p1[0] + p1[1];
        lsum1 += p0[2] + p0[3] + p1[2] + p1[3];
        uint32_t ph[4], pl[4];
        pack2(p0[0], p0[1], ph[0], pl[0]);
        pack2(p0[2], p0[3], ph[1], pl[1]);
        pack2(p1[0], p1[1], ph[2], pl[2]);
        pack2(p1[2], p1[3], ph[3], pl[3]);

        #pragma unroll
        for (int dp = 0; dp < 4; dp++) {
            uint32_t vh4[4], vl4[4];
            ldsm4t(vh4, vh_b + j0b + dp * 32);
            ldsm4t(vl4, vl_b + j0b + dp * 32);
            #pragma unroll
            for (int h = 0; h < 2; h++) {
                int dt = dp * 2 + h, o = h * 2;
                uint32_t bvh[2] = {vh4[o], vh4[o + 1]};
                uint32_t bvl[2] = {vl4[o], vl4[o + 1]};
                mma_bf16(O[dt], ph, bvh);
                mma_bf16(O[dt], pl, bvh);
                mma_bf16(O[dt], ph, bvl);
            }
        }
    }

    // Normalize and store.
    lsum0 += __shfl_xor_sync(0xffffffffu, lsum0, 1);
    lsum0 += __shfl_xor_sync(0xffffffffu, lsum0, 2);
    lsum1 += __shfl_xor_sync(0xffffffffu, lsum1, 1);
    lsum1 += __shfl_xor_sync(0xffffffffu, lsum1, 2);
    const float inv0 = 1.f / lsum0, inv1 = 1.f / lsum1;
    float* o0 = out + base + (size_t)(q0 + g) * HD;
    float* o1 = out + base + (size_t)(q0 + g + 8) * HD;
    #pragma unroll
    for (int dt = 0; dt < 8; dt++) {
        int d = dt * 8 + 2 * t;
        *(float2*)(o0 + d) = make_float2(O[dt][0] * inv0, O[dt][1] * inv0);
        *(float2*)(o1 + d) = make_float2(O[dt][2] * inv1, O[dt][3] * inv1);
    }
}

extern "C" void kernel_launch(void* const* d_in, const int* in_sizes, int n_in,
                              void* d_out, int out_size)
{
    // metadata order follows setup_inputs dict: input_tensor, Wk, Wq, Wv
    const float* X  = (const float*)d_in[0];
    const float* Wk = (const float*)d_in[1];
    const float* Wq = (const float*)d_in[2];
    const float* Wv = (const float*)d_in[3];
    float* out = (float*)d_out;

    const int proj_smem = (2 * 128 * PA + 2 * NTOT * PA) * 2;  // 71680 B
    const int attn_smem = 6 * SEQ * KP * 2;                    // 221184 B
    cudaFuncSetAttribute(proj_kernel,
                         cudaFuncAttributeMaxDynamicSharedMemorySize, proj_smem);
    cudaFuncSetAttribute(attn_kernel,
                         cudaFuncAttributeMaxDynamicSharedMemorySize, attn_smem);

    prep_kernel<<<NTOT * EMBED / 256, 256>>>(Wq, Wk, Wv);
    proj_kernel<<<M_TOTAL / 128, 256, proj_smem>>>(X);
    attn_kernel<<<BATCH, 512, attn_smem>>>(out);
}